// round 1
// baseline (speedup 1.0000x reference)
#include <cuda_runtime.h>
#include <cstddef>

#define N_PTS   32768
#define K_CODES 8192
#define DIM     256
#define DECAYF  0.99f
#define EPSF    1e-5f

#define BM 64
#define BN 64
#define DCH 16

// scratch (no allocations allowed)
__device__ float g_c2[K_CODES];
__device__ float g_n;

// ---------------------------------------------------------------------------
// c2[k] = sum_d codebook[k][d]^2   (one warp per code)
// ---------------------------------------------------------------------------
__global__ void k_c2(const float* __restrict__ cb) {
    int warp = (blockIdx.x * blockDim.x + threadIdx.x) >> 5;
    int lane = threadIdx.x & 31;
    if (warp >= K_CODES) return;
    const float* row = cb + (size_t)warp * DIM;
    float s = 0.0f;
    #pragma unroll
    for (int d = 0; d < DIM / 32; d++) {
        float v = row[lane + d * 32];
        s += v * v;
    }
    #pragma unroll
    for (int o = 16; o; o >>= 1) s += __shfl_xor_sync(0xffffffffu, s, o);
    if (lane == 0) g_c2[warp] = s;
}

// ---------------------------------------------------------------------------
// init EMA targets: out_avg = emb_avg*decay ; out_cs = cluster_size*decay
// ---------------------------------------------------------------------------
__global__ void k_init(const float* __restrict__ emb_avg,
                       const float* __restrict__ cs_in,
                       float* __restrict__ out_avg,
                       float* __restrict__ out_cs) {
    size_t i = (size_t)blockIdx.x * blockDim.x + threadIdx.x;
    if (i < (size_t)K_CODES * DIM) out_avg[i] = emb_avg[i] * DECAYF;
    if (i < (size_t)K_CODES)       out_cs[i]  = cs_in[i]  * DECAYF;
}

// ---------------------------------------------------------------------------
// fused distance + argmin + gather + EMA scatter
// grid: N/BM blocks, 256 threads (16x16), dynamic smem
// ---------------------------------------------------------------------------
__global__ void __launch_bounds__(256, 2) k_dist(
    const float* __restrict__ z, const float* __restrict__ cb,
    float* __restrict__ out_q, float* __restrict__ out_idx,
    float* __restrict__ out_avg, float* __restrict__ out_cs)
{
    extern __shared__ float sm[];
    float* zs    = sm;                         // [BM][257]
    float* cs    = zs + BM * 257;              // [BN][17]
    float* red_v = cs + BN * 17;               // [BM][16]
    int*   red_i = (int*)(red_v + BM * 16);    // [BM][16]
    int*   s_idx = red_i + BM * 16;            // [BM]

    const int t  = threadIdx.x;
    const int tx = t & 15;
    const int ty = t >> 4;
    const int row0 = blockIdx.x * BM;

    // load z tile (64 rows x 256) into shared, padded stride 257
    for (int i = t; i < BM * (DIM / 4); i += 256) {
        int r  = i >> 6;          // DIM/4 = 64 float4 per row
        int c4 = i & 63;
        float4 v = ((const float4*)(z + (size_t)(row0 + r) * DIM))[c4];
        float* dst = zs + r * 257 + c4 * 4;
        dst[0] = v.x; dst[1] = v.y; dst[2] = v.z; dst[3] = v.w;
    }
    __syncthreads();

    float best[4];
    int   bidx[4];
    #pragma unroll
    for (int i = 0; i < 4; i++) { best[i] = 3.4e38f; bidx[i] = 0; }

    for (int ct = 0; ct < K_CODES / BN; ct++) {
        const int codeBase = ct * BN;
        float acc[4][4];
        #pragma unroll
        for (int i = 0; i < 4; i++)
            #pragma unroll
            for (int j = 0; j < 4; j++) acc[i][j] = 0.0f;

        for (int d0 = 0; d0 < DIM; d0 += DCH) {
            __syncthreads();
            {   // load 64 codes x 16 d chunk, padded stride 17
                int c   = t >> 2;           // 0..63
                int dd4 = (t & 3) * 4;      // 0,4,8,12
                float4 v = *(const float4*)(cb + (size_t)(codeBase + c) * DIM + d0 + dd4);
                float* dst = cs + c * 17 + dd4;
                dst[0] = v.x; dst[1] = v.y; dst[2] = v.z; dst[3] = v.w;
            }
            __syncthreads();
            #pragma unroll
            for (int dd = 0; dd < DCH; dd++) {
                float zr[4], cv[4];
                #pragma unroll
                for (int i = 0; i < 4; i++) zr[i] = zs[(ty * 4 + i) * 257 + d0 + dd];
                #pragma unroll
                for (int j = 0; j < 4; j++) cv[j] = cs[(tx * 4 + j) * 17 + dd];
                #pragma unroll
                for (int i = 0; i < 4; i++)
                    #pragma unroll
                    for (int j = 0; j < 4; j++)
                        acc[i][j] += zr[i] * cv[j];
            }
        }
        // fold tile into running argmin (codes visited in ascending order ->
        // strict < keeps the earliest/lowest index, matching jnp.argmin)
        #pragma unroll
        for (int j = 0; j < 4; j++) {
            int code = codeBase + tx * 4 + j;
            float c2v = g_c2[code];
            #pragma unroll
            for (int i = 0; i < 4; i++) {
                float dist = c2v - 2.0f * acc[i][j];
                if (dist < best[i]) { best[i] = dist; bidx[i] = code; }
            }
        }
    }

    __syncthreads();
    #pragma unroll
    for (int i = 0; i < 4; i++) {
        red_v[(ty * 4 + i) * 16 + tx] = best[i];
        red_i[(ty * 4 + i) * 16 + tx] = bidx[i];
    }
    __syncthreads();

    if (t < BM) {
        float bv = red_v[t * 16];
        int   bi = red_i[t * 16];
        #pragma unroll
        for (int x = 1; x < 16; x++) {
            float v = red_v[t * 16 + x];
            int  ii = red_i[t * 16 + x];
            if (v < bv || (v == bv && ii < bi)) { bv = v; bi = ii; }
        }
        s_idx[t] = bi;
        out_idx[row0 + t] = (float)bi;
        atomicAdd(&out_cs[bi], 1.0f - DECAYF);
    }
    __syncthreads();

    // epilogue: gather quantized rows + EMA scatter of z (t spans DIM=256)
    const float sc = 1.0f - DECAYF;
    for (int r = 0; r < BM; r++) {
        int idx = s_idx[r];
        float q = cb[(size_t)idx * DIM + t];
        out_q[(size_t)(row0 + r) * DIM + t] = q;
        atomicAdd(&out_avg[(size_t)idx * DIM + t], zs[r * 257 + t] * sc);
    }
}

// ---------------------------------------------------------------------------
// n = sum(new_cluster_size)   (single block)
// ---------------------------------------------------------------------------
__global__ void k_sumn(const float* __restrict__ out_cs) {
    __shared__ float sh[256];
    float s = 0.0f;
    for (int i = threadIdx.x; i < K_CODES; i += 256) s += out_cs[i];
    sh[threadIdx.x] = s;
    __syncthreads();
    for (int o = 128; o; o >>= 1) {
        if (threadIdx.x < o) sh[threadIdx.x] += sh[threadIdx.x + o];
        __syncthreads();
    }
    if (threadIdx.x == 0) g_n = sh[0];
}

// ---------------------------------------------------------------------------
// new_codebook = new_embedding_avg / smoothed
// ---------------------------------------------------------------------------
__global__ void k_final(const float* __restrict__ out_avg,
                        const float* __restrict__ out_cs,
                        float* __restrict__ out_cb) {
    int k = blockIdx.x;
    float n = g_n;
    float smoothed = (out_cs[k] + EPSF) / (n + (float)K_CODES * EPSF) * n;
    size_t off = (size_t)k * DIM + threadIdx.x;
    out_cb[off] = out_avg[off] / smoothed;
}

// ---------------------------------------------------------------------------
extern "C" void kernel_launch(void* const* d_in, const int* in_sizes, int n_in,
                              void* d_out, int out_size) {
    const float* z_flat   = (const float*)d_in[0];   // (N, D)
    const float* codebook = (const float*)d_in[1];   // (K, D)
    const float* emb_avg  = (const float*)d_in[2];   // (K, D)
    const float* cs_in    = (const float*)d_in[3];   // (K,)

    float* out_q   = (float*)d_out;                          // N*D
    float* out_idx = out_q   + (size_t)N_PTS * DIM;          // N
    float* out_cb  = out_idx + N_PTS;                        // K*D
    float* out_avg = out_cb  + (size_t)K_CODES * DIM;        // K*D
    float* out_cs  = out_avg + (size_t)K_CODES * DIM;        // K

    const int smem = (BM * 257 + BN * 17 + BM * 16) * 4 + BM * 16 * 4 + BM * 4;
    cudaFuncSetAttribute(k_dist, cudaFuncAttributeMaxDynamicSharedMemorySize, smem);

    k_c2<<<K_CODES / 8, 256>>>(codebook);
    k_init<<<(K_CODES * DIM + 255) / 256, 256>>>(emb_avg, cs_in, out_avg, out_cs);
    k_dist<<<N_PTS / BM, 256, smem>>>(z_flat, codebook, out_q, out_idx, out_avg, out_cs);
    k_sumn<<<1, 256>>>(out_cs);
    k_final<<<K_CODES, DIM>>>(out_avg, out_cs, out_cb);
}

// round 3
// speedup vs baseline: 2.2972x; 2.2972x over previous
#include <cuda_runtime.h>
#include <cuda_fp16.h>
#include <cstdint>
#include <cstddef>

#define N_PTS   32768
#define K_CODES 8192
#define DIM     256
#define KP      768              // split K': [hi|hi|lo] x [hi|lo|hi]
#define DECAYF  0.99f
#define EPSF    1e-5f

#define BM 128                   // z rows per block
#define BN 128                   // codes per n-tile
#define KC 32                    // k per chunk
#define NKC (KP / KC)            // 24
#define NNT (K_CODES / BN)       // 64

// dynamic smem layout (bytes)
#define SM_A     0               // 8 mtiles * 48 ksteps * 32 lanes * 16B = 196608
#define SM_B     196608          // 2 bufs * 10240 (128 rows * 80B padded)
#define SM_BSZ   10240
#define SM_C2    217088          // float[128]
#define SM_RV    217600          // float[128][2]
#define SM_RI    218624          // int[128][2]
#define SM_IDX   219648          // int[128]
#define SM_TOTAL 220160

// device scratch (allocation-free rule)
__device__ __half g_za[(size_t)N_PTS   * KP];   // 48 MB
__device__ __half g_cb[(size_t)K_CODES * KP];   // 12 MB
__device__ float  g_c2[K_CODES];
__device__ float  g_n;

__device__ __forceinline__ uint32_t s2u(const void* p) {
    uint32_t a;
    asm("{ .reg .u64 t; cvta.to.shared.u64 t, %1; cvt.u32.u64 %0, t; }"
        : "=r"(a) : "l"(p));
    return a;
}

// ---------------------------------------------------------------------------
// split z: row -> [hi(256) | hi(256) | lo(256)]
// ---------------------------------------------------------------------------
__global__ void k_split_z(const float* __restrict__ z) {
    size_t i = (size_t)blockIdx.x * blockDim.x + threadIdx.x;
    if (i >= (size_t)N_PTS * DIM) return;
    size_t row = i >> 8, c = i & 255;
    float v = z[i];
    __half h = __float2half_rn(v);
    __half l = __float2half_rn(v - __half2float(h));
    __half* base = g_za + row * KP;
    base[c] = h; base[256 + c] = h; base[512 + c] = l;
}

// split codebook: row -> [hi | lo | hi]; also exact fp32 c2 (warp per code)
__global__ void k_split_c(const float* __restrict__ cbk) {
    int code = (blockIdx.x * blockDim.x + threadIdx.x) >> 5;
    int lane = threadIdx.x & 31;
    if (code >= K_CODES) return;
    const float* row = cbk + (size_t)code * DIM;
    __half* base = g_cb + (size_t)code * KP;
    float s = 0.0f;
    #pragma unroll
    for (int d = 0; d < DIM / 32; d++) {
        int c = lane + d * 32;
        float v = row[c];
        s += v * v;
        __half h = __float2half_rn(v);
        __half l = __float2half_rn(v - __half2float(h));
        base[c] = h; base[256 + c] = l; base[512 + c] = h;
    }
    #pragma unroll
    for (int o = 16; o; o >>= 1) s += __shfl_xor_sync(0xffffffffu, s, o);
    if (lane == 0) g_c2[code] = s;
}

// ---------------------------------------------------------------------------
__global__ void k_init(const float* __restrict__ emb_avg,
                       const float* __restrict__ cs_in,
                       float* __restrict__ out_avg,
                       float* __restrict__ out_cs) {
    size_t i = (size_t)blockIdx.x * blockDim.x + threadIdx.x;
    if (i < (size_t)K_CODES * DIM) out_avg[i] = emb_avg[i] * DECAYF;
    if (i < (size_t)K_CODES)       out_cs[i]  = cs_in[i]  * DECAYF;
}

// ---------------------------------------------------------------------------
// HMMA distance GEMM + fused argmin + gather + EMA scatter
// 256 threads = 8 warps: warp_m = wid&3 (32 rows each), warp_n = wid>>2 (64 codes)
// ---------------------------------------------------------------------------
__global__ void __launch_bounds__(256, 1) k_tc(
    const float* __restrict__ z, const float* __restrict__ cb,
    float* __restrict__ out_q, float* __restrict__ out_idx,
    float* __restrict__ out_avg, float* __restrict__ out_cs)
{
    extern __shared__ __align__(16) char sm[];
    const uint32_t sb = s2u(sm);
    const int tid  = threadIdx.x;
    const int lane = tid & 31;
    const int wid  = tid >> 5;
    const int wm   = wid & 3;
    const int wn   = wid >> 2;
    const int row0 = blockIdx.x * BM;

    // ---- stage A (128 x 768 halfs) in pre-fragment layout, one tile per warp ----
    for (int t = wid; t < 8 * 48; t += 8) {          // t = tmt*48 + ks
        const int tmt = t / 48, ks = t - tmt * 48;
        const __half* g = g_za + (size_t)(row0 + tmt * 16 + (lane >> 2)) * KP
                        + ks * 16 + (lane & 3) * 2;
        uint32_t r0 = *(const uint32_t*)g;
        uint32_t r1 = *(const uint32_t*)(g + 8 * KP);
        uint32_t r2 = *(const uint32_t*)(g + 8);
        uint32_t r3 = *(const uint32_t*)(g + 8 * KP + 8);
        uint32_t addr = sb + SM_A + (uint32_t)(t * 32 + lane) * 16;
        asm volatile("st.shared.v4.b32 [%0], {%1,%2,%3,%4};"
                     :: "r"(addr), "r"(r0), "r"(r1), "r"(r2), "r"(r3));
    }

    float bv[4];
    int   bi[4];
    #pragma unroll
    for (int s = 0; s < 4; s++) { bv[s] = 3.4e38f; bi[s] = 0; }

    float* c2s = (float*)(sm + SM_C2);

    for (int nt0 = 0; nt0 < NNT; nt0++) {
        const int code0 = nt0 * BN;

        if (tid < BN) c2s[tid] = g_c2[code0 + tid];

        // prefetch chunk 0
        {
            const int u0 = tid, u1 = tid + 256;
            int r = u0 >> 2, s = u0 & 3;
            const __half* src = g_cb + (size_t)(code0 + r) * KP + s * 8;
            uint32_t dst = sb + SM_B + (uint32_t)(r * 80 + s * 16);
            asm volatile("cp.async.cg.shared.global [%0], [%1], 16;"
                         :: "r"(dst), "l"(src));
            r = u1 >> 2; s = u1 & 3;
            src = g_cb + (size_t)(code0 + r) * KP + s * 8;
            dst = sb + SM_B + (uint32_t)(r * 80 + s * 16);
            asm volatile("cp.async.cg.shared.global [%0], [%1], 16;"
                         :: "r"(dst), "l"(src));
            asm volatile("cp.async.commit_group;");
        }

        float acc[2][8][4];
        #pragma unroll
        for (int mt = 0; mt < 2; mt++)
            #pragma unroll
            for (int nt = 0; nt < 8; nt++)
                #pragma unroll
                for (int q = 0; q < 4; q++) acc[mt][nt][q] = 0.0f;

        for (int kc = 0; kc < NKC; kc++) {
            if (kc + 1 < NKC) {                      // prefetch next chunk
                const uint32_t bb = sb + SM_B + ((kc + 1) & 1) * SM_BSZ;
                const int koff = (kc + 1) * KC;
                #pragma unroll
                for (int uu = 0; uu < 2; uu++) {
                    int u = tid + uu * 256;
                    int r = u >> 2, s = u & 3;
                    const __half* src = g_cb + (size_t)(code0 + r) * KP + koff + s * 8;
                    uint32_t dst = bb + (uint32_t)(r * 80 + s * 16);
                    asm volatile("cp.async.cg.shared.global [%0], [%1], 16;"
                                 :: "r"(dst), "l"(src));
                }
                asm volatile("cp.async.commit_group;");
                asm volatile("cp.async.wait_group 1;");
            } else {
                asm volatile("cp.async.wait_group 0;");
            }
            __syncthreads();

            const uint32_t bbase = sb + SM_B + (kc & 1) * SM_BSZ;
            #pragma unroll
            for (int k2 = 0; k2 < 2; k2++) {
                const int ks = kc * 2 + k2;
                uint32_t a0[4], a1[4];
                {
                    uint32_t addr = sb + SM_A
                        + (uint32_t)(((wm * 2 + 0) * 48 + ks) * 32 + lane) * 16;
                    asm volatile("ld.shared.v4.b32 {%0,%1,%2,%3}, [%4];"
                                 : "=r"(a0[0]), "=r"(a0[1]), "=r"(a0[2]), "=r"(a0[3])
                                 : "r"(addr));
                    addr = sb + SM_A
                        + (uint32_t)(((wm * 2 + 1) * 48 + ks) * 32 + lane) * 16;
                    asm volatile("ld.shared.v4.b32 {%0,%1,%2,%3}, [%4];"
                                 : "=r"(a1[0]), "=r"(a1[1]), "=r"(a1[2]), "=r"(a1[3])
                                 : "r"(addr));
                }
                uint32_t b[16];
                #pragma unroll
                for (int j = 0; j < 4; j++) {
                    // matrices: (nt=2j,kh0),(nt=2j,kh1),(nt=2j+1,kh0),(nt=2j+1,kh1)
                    int gq = lane >> 3, rr = lane & 7;
                    uint32_t addr = bbase
                        + (uint32_t)((wn * 64 + (2 * j + (gq >> 1)) * 8 + rr) * 80
                                     + k2 * 32 + (gq & 1) * 16);
                    asm volatile("ldmatrix.sync.aligned.m8n8.x4.shared.b16 "
                                 "{%0,%1,%2,%3}, [%4];"
                                 : "=r"(b[4 * j]), "=r"(b[4 * j + 1]),
                                   "=r"(b[4 * j + 2]), "=r"(b[4 * j + 3])
                                 : "r"(addr));
                }
                #pragma unroll
                for (int nt = 0; nt < 8; nt++) {
                    const int bj = (nt >> 1) * 4 + (nt & 1) * 2;
                    asm volatile(
                        "mma.sync.aligned.m16n8k16.row.col.f32.f16.f16.f32 "
                        "{%0,%1,%2,%3}, {%4,%5,%6,%7}, {%8,%9}, {%0,%1,%2,%3};"
                        : "+f"(acc[0][nt][0]), "+f"(acc[0][nt][1]),
                          "+f"(acc[0][nt][2]), "+f"(acc[0][nt][3])
                        : "r"(a0[0]), "r"(a0[1]), "r"(a0[2]), "r"(a0[3]),
                          "r"(b[bj]), "r"(b[bj + 1]));
                    asm volatile(
                        "mma.sync.aligned.m16n8k16.row.col.f32.f16.f16.f32 "
                        "{%0,%1,%2,%3}, {%4,%5,%6,%7}, {%8,%9}, {%0,%1,%2,%3};"
                        : "+f"(acc[1][nt][0]), "+f"(acc[1][nt][1]),
                          "+f"(acc[1][nt][2]), "+f"(acc[1][nt][3])
                        : "r"(a1[0]), "r"(a1[1]), "r"(a1[2]), "r"(a1[3]),
                          "r"(b[bj]), "r"(b[bj + 1]));
                }
            }
            __syncthreads();
        }

        // fold: dist = c2 - 2*dot ; slot s = mt*2 + (q>>1)
        #pragma unroll
        for (int mt = 0; mt < 2; mt++)
            #pragma unroll
            for (int nt = 0; nt < 8; nt++)
                #pragma unroll
                for (int q = 0; q < 4; q++) {
                    int cc = wn * 64 + nt * 8 + (lane & 3) * 2 + (q & 1);
                    float d = fmaf(acc[mt][nt][q], -2.0f, c2s[cc]);
                    int s = mt * 2 + (q >> 1);
                    int code = code0 + cc;
                    if (d < bv[s]) { bv[s] = d; bi[s] = code; }
                }
        __syncthreads();   // protect c2s / B bufs before next tile
    }

    // ---- reduce: lanes within 4-group hold disjoint code columns ----
    #pragma unroll
    for (int s = 0; s < 4; s++) {
        #pragma unroll
        for (int o = 1; o < 4; o <<= 1) {
            float v = __shfl_xor_sync(0xffffffffu, bv[s], o);
            int   i = __shfl_xor_sync(0xffffffffu, bi[s], o);
            if (v < bv[s] || (v == bv[s] && i < bi[s])) { bv[s] = v; bi[s] = i; }
        }
        if ((lane & 3) == 0) {
            int row = wm * 32 + s * 8 + (lane >> 2);
            ((float*)(sm + SM_RV))[row * 2 + wn] = bv[s];
            ((int*)  (sm + SM_RI))[row * 2 + wn] = bi[s];
        }
    }
    __syncthreads();

    int* sidx = (int*)(sm + SM_IDX);
    if (tid < BM) {
        float v0 = ((float*)(sm + SM_RV))[tid * 2];
        float v1 = ((float*)(sm + SM_RV))[tid * 2 + 1];
        int   i0 = ((int*)(sm + SM_RI))[tid * 2];
        int   i1 = ((int*)(sm + SM_RI))[tid * 2 + 1];
        int  bst = (v1 < v0 || (v1 == v0 && i1 < i0)) ? i1 : i0;
        sidx[tid] = bst;
        out_idx[row0 + tid] = (float)bst;
        atomicAdd(&out_cs[bst], 1.0f - DECAYF);
    }
    __syncthreads();

    // ---- gather quantized + EMA scatter (256 threads cover DIM=256) ----
    const float sc = 1.0f - DECAYF;
    for (int r = 0; r < BM; r++) {
        int idx = sidx[r];
        float q = cb[(size_t)idx * DIM + tid];
        out_q[(size_t)(row0 + r) * DIM + tid] = q;
        atomicAdd(&out_avg[(size_t)idx * DIM + tid],
                  z[(size_t)(row0 + r) * DIM + tid] * sc);
    }
}

// ---------------------------------------------------------------------------
__global__ void k_sumn(const float* __restrict__ out_cs) {
    __shared__ float sh[256];
    float s = 0.0f;
    for (int i = threadIdx.x; i < K_CODES; i += 256) s += out_cs[i];
    sh[threadIdx.x] = s;
    __syncthreads();
    for (int o = 128; o; o >>= 1) {
        if (threadIdx.x < o) sh[threadIdx.x] += sh[threadIdx.x + o];
        __syncthreads();
    }
    if (threadIdx.x == 0) g_n = sh[0];
}

__global__ void k_final(const float* __restrict__ out_avg,
                        const float* __restrict__ out_cs,
                        float* __restrict__ out_cb) {
    int k = blockIdx.x;
    float n = g_n;
    float smoothed = (out_cs[k] + EPSF) / (n + (float)K_CODES * EPSF) * n;
    size_t off = (size_t)k * DIM + threadIdx.x;
    out_cb[off] = out_avg[off] / smoothed;
}

// ---------------------------------------------------------------------------
extern "C" void kernel_launch(void* const* d_in, const int* in_sizes, int n_in,
                              void* d_out, int out_size) {
    const float* z_flat   = (const float*)d_in[0];
    const float* codebook = (const float*)d_in[1];
    const float* emb_avg  = (const float*)d_in[2];
    const float* cs_in    = (const float*)d_in[3];

    float* out_q   = (float*)d_out;
    float* out_idx = out_q   + (size_t)N_PTS * DIM;
    float* out_cb  = out_idx + N_PTS;
    float* out_avg = out_cb  + (size_t)K_CODES * DIM;
    float* out_cs  = out_avg + (size_t)K_CODES * DIM;

    cudaFuncSetAttribute(k_tc, cudaFuncAttributeMaxDynamicSharedMemorySize, SM_TOTAL);

    k_split_z<<<(N_PTS * DIM + 255) / 256, 256>>>(z_flat);
    k_split_c<<<K_CODES / 8, 256>>>(codebook);
    k_init<<<(K_CODES * DIM + 255) / 256, 256>>>(emb_avg, cs_in, out_avg, out_cs);
    k_tc<<<N_PTS / BM, 256, SM_TOTAL>>>(z_flat, codebook,
                                        out_q, out_idx, out_avg, out_cs);
    k_sumn<<<1, 256>>>(out_cs);
    k_final<<<K_CODES, DIM>>>(out_avg, out_cs, out_cb);
}

// round 4
// speedup vs baseline: 3.2744x; 1.4253x over previous
#include <cuda_runtime.h>
#include <cuda_fp16.h>
#include <cstdint>
#include <cstddef>

#define N_PTS   32768
#define K_CODES 8192
#define DIM     256
#define DECAYF  0.99f
#define EPSF    1e-5f

#define BM 128
#define BN 128
#define KC 32
#define NKC (DIM / KC)           // 8 chunks per n-tile
#define NNT (K_CODES / BN)       // 64 n-tiles
#define NGC (NNT * NKC)          // 512 chunks total

// dynamic smem layout for k_approx (bytes)
#define SM_A     0               // 8 mtiles * 16 ksteps * 32 lanes * 16B = 65536
#define SM_B     65536           // 2 bufs * 10240 (128 rows * 80B padded)
#define SM_BSZ   10240
#define SM_C2    86016           // float[128]
#define SM_RV    86528           // float[128][2] best
#define SM_RS    87552           // float[128][2] second
#define SM_RI    88576           // int[128][2]
#define SM_TOTAL 89600

// device scratch
__device__ __half g_zh[(size_t)N_PTS * DIM];     // 16 MB
__device__ __half g_ch[(size_t)K_CODES * DIM];   // 4 MB
__device__ float  g_c2[K_CODES];
__device__ unsigned g_stats[4];   // 0:maxZh2 1:maxZl2 2:maxC2 3:maxCl2 (float bits)
__device__ int    g_ucnt;
__device__ int    g_ulist[N_PTS];
__device__ unsigned long long g_min64[N_PTS];
__device__ int    g_idx[N_PTS];
__device__ float  g_n;

__device__ __forceinline__ uint32_t s2u(const void* p) {
    uint32_t a;
    asm("{ .reg .u64 t; cvta.to.shared.u64 t, %1; cvt.u32.u64 %0, t; }"
        : "=r"(a) : "l"(p));
    return a;
}
__device__ __forceinline__ void atomicMaxF(unsigned* addr, float v) {
    atomicMax(addr, __float_as_uint(v));     // v >= 0 -> uint order == float order
}
__device__ __forceinline__ unsigned mapf(float d) {
    unsigned u = __float_as_uint(d);
    return (u & 0x80000000u) ? ~u : (u | 0x80000000u);
}

// ---------------------------------------------------------------------------
__global__ void k_zero() {
    if (threadIdx.x == 0) g_ucnt = 0;
    if (threadIdx.x < 4) g_stats[threadIdx.x] = 0;
}

// split z -> zh; per-row norms of zh, zl -> global maxima. warp per row.
__global__ void k_split_z(const float* __restrict__ z) {
    __shared__ float sh[2];
    if (threadIdx.x < 2) sh[threadIdx.x] = 0.0f;
    __syncthreads();
    int row  = (blockIdx.x * blockDim.x + threadIdx.x) >> 5;
    int lane = threadIdx.x & 31;
    float h2 = 0.0f, l2 = 0.0f;
    const float* src = z + (size_t)row * DIM;
    __half* dst = g_zh + (size_t)row * DIM;
    #pragma unroll
    for (int d = 0; d < DIM / 32; d++) {
        int c = lane + d * 32;
        float v = src[c];
        __half h = __float2half_rn(v);
        float hf = __half2float(h);
        float lf = v - hf;
        dst[c] = h;
        h2 += hf * hf; l2 += lf * lf;
    }
    #pragma unroll
    for (int o = 16; o; o >>= 1) {
        h2 += __shfl_xor_sync(0xffffffffu, h2, o);
        l2 += __shfl_xor_sync(0xffffffffu, l2, o);
    }
    if (lane == 0) {
        atomicMaxF((unsigned*)&sh[0], h2);   // smem atomic on float-bits (>=0)
        atomicMaxF((unsigned*)&sh[1], l2);
    }
    __syncthreads();
    if (threadIdx.x == 0) atomicMaxF(&g_stats[0], sh[0]);
    if (threadIdx.x == 1) atomicMaxF(&g_stats[1], sh[1]);
}

// split codebook -> ch; exact c2; norm maxima. warp per code.
__global__ void k_split_c(const float* __restrict__ cbk) {
    __shared__ float sh[2];
    if (threadIdx.x < 2) sh[threadIdx.x] = 0.0f;
    __syncthreads();
    int code = (blockIdx.x * blockDim.x + threadIdx.x) >> 5;
    int lane = threadIdx.x & 31;
    const float* src = cbk + (size_t)code * DIM;
    __half* dst = g_ch + (size_t)code * DIM;
    float c2 = 0.0f, l2 = 0.0f;
    #pragma unroll
    for (int d = 0; d < DIM / 32; d++) {
        int c = lane + d * 32;
        float v = src[c];
        __half h = __float2half_rn(v);
        float lf = v - __half2float(h);
        dst[c] = h;
        c2 += v * v; l2 += lf * lf;
    }
    #pragma unroll
    for (int o = 16; o; o >>= 1) {
        c2 += __shfl_xor_sync(0xffffffffu, c2, o);
        l2 += __shfl_xor_sync(0xffffffffu, l2, o);
    }
    if (lane == 0) {
        g_c2[code] = c2;
        atomicMaxF((unsigned*)&sh[0], c2);
        atomicMaxF((unsigned*)&sh[1], l2);
    }
    __syncthreads();
    if (threadIdx.x == 0) atomicMaxF(&g_stats[2], sh[0]);
    if (threadIdx.x == 1) atomicMaxF(&g_stats[3], sh[1]);
}

// ---------------------------------------------------------------------------
__global__ void k_init(const float* __restrict__ emb_avg,
                       const float* __restrict__ cs_in,
                       float* __restrict__ out_avg,
                       float* __restrict__ out_cs) {
    size_t i = (size_t)blockIdx.x * blockDim.x + threadIdx.x;
    if (i < (size_t)K_CODES * DIM) out_avg[i] = emb_avg[i] * DECAYF;
    if (i < (size_t)K_CODES)       out_cs[i]  = cs_in[i]  * DECAYF;
}

// ---------------------------------------------------------------------------
// fp16 hi*hi GEMM + top-2 argmin with certified margin
// ---------------------------------------------------------------------------
__global__ void __launch_bounds__(256, 2) k_approx(float* __restrict__ out_idx)
{
    extern __shared__ __align__(16) char sm[];
    const uint32_t sb = s2u(sm);
    const int tid  = threadIdx.x;
    const int lane = tid & 31;
    const int wid  = tid >> 5;
    const int wm   = wid & 3;
    const int wn   = wid >> 2;
    const int row0 = blockIdx.x * BM;

    // stage A (128 x 256 halfs) pre-fragment layout
    for (int t = wid; t < 8 * 16; t += 8) {          // t = tmt*16 + ks
        const int tmt = t >> 4, ks = t & 15;
        const __half* g = g_zh + (size_t)(row0 + tmt * 16 + (lane >> 2)) * DIM
                        + ks * 16 + (lane & 3) * 2;
        uint32_t r0 = *(const uint32_t*)g;
        uint32_t r1 = *(const uint32_t*)(g + 8 * DIM);
        uint32_t r2 = *(const uint32_t*)(g + 8);
        uint32_t r3 = *(const uint32_t*)(g + 8 * DIM + 8);
        uint32_t addr = sb + SM_A + (uint32_t)(t * 32 + lane) * 16;
        asm volatile("st.shared.v4.b32 [%0], {%1,%2,%3,%4};"
                     :: "r"(addr), "r"(r0), "r"(r1), "r"(r2), "r"(r3));
    }

    float bv[4], sv[4];
    int   bi[4];
    #pragma unroll
    for (int s = 0; s < 4; s++) { bv[s] = 3.4e38f; sv[s] = 3.4e38f; bi[s] = 0; }

    float* c2s = (float*)(sm + SM_C2);

    // prefetch chunk 0
    {
        #pragma unroll
        for (int uu = 0; uu < 2; uu++) {
            int u = tid + uu * 256;
            int r = u >> 2, s = u & 3;
            const __half* src = g_ch + (size_t)r * DIM + s * 8;
            uint32_t dst = sb + SM_B + (uint32_t)(r * 80 + s * 16);
            asm volatile("cp.async.cg.shared.global [%0], [%1], 16;"
                         :: "r"(dst), "l"(src));
        }
        asm volatile("cp.async.commit_group;");
    }

    for (int nt0 = 0; nt0 < NNT; nt0++) {
        const int code0 = nt0 * BN;
        if (tid < BN) c2s[tid] = g_c2[code0 + tid];

        float acc[2][8][4];
        #pragma unroll
        for (int mt = 0; mt < 2; mt++)
            #pragma unroll
            for (int nt = 0; nt < 8; nt++)
                #pragma unroll
                for (int q = 0; q < 4; q++) acc[mt][nt][q] = 0.0f;

        for (int kc = 0; kc < NKC; kc++) {
            const int gc = nt0 * NKC + kc;
            if (gc + 1 < NGC) {                  // prefetch next chunk (continuous)
                const uint32_t bb = sb + SM_B + ((gc + 1) & 1) * SM_BSZ;
                const int pc0 = ((gc + 1) >> 3) * BN;
                const int pko = ((gc + 1) & 7) * KC;
                #pragma unroll
                for (int uu = 0; uu < 2; uu++) {
                    int u = tid + uu * 256;
                    int r = u >> 2, s = u & 3;
                    const __half* src = g_ch + (size_t)(pc0 + r) * DIM + pko + s * 8;
                    uint32_t dst = bb + (uint32_t)(r * 80 + s * 16);
                    asm volatile("cp.async.cg.shared.global [%0], [%1], 16;"
                                 :: "r"(dst), "l"(src));
                }
                asm volatile("cp.async.commit_group;");
                asm volatile("cp.async.wait_group 1;");
            } else {
                asm volatile("cp.async.wait_group 0;");
            }
            __syncthreads();

            const uint32_t bbase = sb + SM_B + (gc & 1) * SM_BSZ;
            #pragma unroll
            for (int k2 = 0; k2 < 2; k2++) {
                const int ks = kc * 2 + k2;
                uint32_t a0[4], a1[4];
                {
                    uint32_t addr = sb + SM_A
                        + (uint32_t)(((wm * 2 + 0) * 16 + ks) * 32 + lane) * 16;
                    asm volatile("ld.shared.v4.b32 {%0,%1,%2,%3}, [%4];"
                                 : "=r"(a0[0]), "=r"(a0[1]), "=r"(a0[2]), "=r"(a0[3])
                                 : "r"(addr));
                    addr = sb + SM_A
                        + (uint32_t)(((wm * 2 + 1) * 16 + ks) * 32 + lane) * 16;
                    asm volatile("ld.shared.v4.b32 {%0,%1,%2,%3}, [%4];"
                                 : "=r"(a1[0]), "=r"(a1[1]), "=r"(a1[2]), "=r"(a1[3])
                                 : "r"(addr));
                }
                uint32_t b[16];
                #pragma unroll
                for (int j = 0; j < 4; j++) {
                    int gq = lane >> 3, rr = lane & 7;
                    uint32_t addr = bbase
                        + (uint32_t)((wn * 64 + (2 * j + (gq >> 1)) * 8 + rr) * 80
                                     + k2 * 32 + (gq & 1) * 16);
                    asm volatile("ldmatrix.sync.aligned.m8n8.x4.shared.b16 "
                                 "{%0,%1,%2,%3}, [%4];"
                                 : "=r"(b[4 * j]), "=r"(b[4 * j + 1]),
                                   "=r"(b[4 * j + 2]), "=r"(b[4 * j + 3])
                                 : "r"(addr));
                }
                #pragma unroll
                for (int nt = 0; nt < 8; nt++) {
                    const int bj = (nt >> 1) * 4 + (nt & 1) * 2;
                    asm volatile(
                        "mma.sync.aligned.m16n8k16.row.col.f32.f16.f16.f32 "
                        "{%0,%1,%2,%3}, {%4,%5,%6,%7}, {%8,%9}, {%0,%1,%2,%3};"
                        : "+f"(acc[0][nt][0]), "+f"(acc[0][nt][1]),
                          "+f"(acc[0][nt][2]), "+f"(acc[0][nt][3])
                        : "r"(a0[0]), "r"(a0[1]), "r"(a0[2]), "r"(a0[3]),
                          "r"(b[bj]), "r"(b[bj + 1]));
                    asm volatile(
                        "mma.sync.aligned.m16n8k16.row.col.f32.f16.f16.f32 "
                        "{%0,%1,%2,%3}, {%4,%5,%6,%7}, {%8,%9}, {%0,%1,%2,%3};"
                        : "+f"(acc[1][nt][0]), "+f"(acc[1][nt][1]),
                          "+f"(acc[1][nt][2]), "+f"(acc[1][nt][3])
                        : "r"(a1[0]), "r"(a1[1]), "r"(a1[2]), "r"(a1[3]),
                          "r"(b[bj]), "r"(b[bj + 1]));
                }
            }
            __syncthreads();
        }

        // fold top-2: dist = c2 - 2*dot
        #pragma unroll
        for (int mt = 0; mt < 2; mt++)
            #pragma unroll
            for (int nt = 0; nt < 8; nt++)
                #pragma unroll
                for (int q = 0; q < 4; q++) {
                    int cc = wn * 64 + nt * 8 + (lane & 3) * 2 + (q & 1);
                    float d = fmaf(acc[mt][nt][q], -2.0f, c2s[cc]);
                    int s = mt * 2 + (q >> 1);
                    if (d < bv[s]) { sv[s] = bv[s]; bv[s] = d; bi[s] = code0 + cc; }
                    else if (d < sv[s]) sv[s] = d;
                }
        __syncthreads();
    }

    // lane reduce (partners hold same rows, different codes)
    #pragma unroll
    for (int s = 0; s < 4; s++) {
        #pragma unroll
        for (int o = 1; o < 4; o <<= 1) {
            float v2 = __shfl_xor_sync(0xffffffffu, bv[s], o);
            float s2 = __shfl_xor_sync(0xffffffffu, sv[s], o);
            int   i2 = __shfl_xor_sync(0xffffffffu, bi[s], o);
            if (v2 < bv[s] || (v2 == bv[s] && i2 < bi[s])) {
                sv[s] = fminf(bv[s], s2); bv[s] = v2; bi[s] = i2;
            } else {
                sv[s] = fminf(sv[s], v2);
            }
        }
        if ((lane & 3) == 0) {
            int row = wm * 32 + s * 8 + (lane >> 2);
            ((float*)(sm + SM_RV))[row * 2 + wn] = bv[s];
            ((float*)(sm + SM_RS))[row * 2 + wn] = sv[s];
            ((int*)  (sm + SM_RI))[row * 2 + wn] = bi[s];
        }
    }
    __syncthreads();

    if (tid < BM) {
        float b1 = ((float*)(sm + SM_RV))[tid * 2],     b2 = ((float*)(sm + SM_RV))[tid * 2 + 1];
        float s1 = ((float*)(sm + SM_RS))[tid * 2],     s2 = ((float*)(sm + SM_RS))[tid * 2 + 1];
        int   i1 = ((int*)  (sm + SM_RI))[tid * 2],     i2 = ((int*)  (sm + SM_RI))[tid * 2 + 1];
        float best, sec; int idx;
        if (b2 < b1 || (b2 == b1 && i2 < i1)) { best = b2; idx = i2; sec = fminf(b1, s2); }
        else                                  { best = b1; idx = i1; sec = fminf(b2, s1); }

        float mZh = sqrtf(__uint_as_float(g_stats[0]));
        float mZl = sqrtf(__uint_as_float(g_stats[1]));
        float mC  = sqrtf(__uint_as_float(g_stats[2]));
        float mCl = sqrtf(__uint_as_float(g_stats[3]));
        float margin = 4.0f * (mZh * mCl + mZl * mC + mZl * mCl) + 0.03f;

        int row = row0 + tid;
        if (sec - best >= margin) {
            g_idx[row] = idx;
            out_idx[row] = (float)idx;
        } else {
            int pos = atomicAdd(&g_ucnt, 1);
            g_ulist[pos] = row;
            g_min64[row] = ~0ull;
        }
    }
}

// ---------------------------------------------------------------------------
// exact fp32 re-rank of uncertain rows (persistent blocks)
// job = (rowgroup of 16) x (1024-code split of 8)
// ---------------------------------------------------------------------------
__global__ void __launch_bounds__(256) k_exact(
    const float* __restrict__ z, const float* __restrict__ cbk)
{
    __shared__ float zs[16 * DIM];
    __shared__ int   rl[16];
    const int tid = threadIdx.x;
    const int ucnt = g_ucnt;
    const int njobs = ((ucnt + 15) >> 4) << 3;

    for (int job = blockIdx.x; job < njobs; job += gridDim.x) {
        const int rg = job >> 3;
        const int cs = job & 7;
        const int nv = min(16, ucnt - rg * 16);

        __syncthreads();
        if (tid < 16) rl[tid] = (tid < nv) ? g_ulist[rg * 16 + tid] : 0;
        __syncthreads();
        for (int r = 0; r < 16; r++) {
            zs[r * DIM + tid] = (r < nv) ? z[(size_t)rl[r] * DIM + tid] : 0.0f;
        }
        __syncthreads();

        #pragma unroll 1
        for (int cc = 0; cc < 4; cc++) {
            const int code = cs * 1024 + cc * 256 + tid;
            const float* crow = cbk + (size_t)code * DIM;
            float dot[16];
            #pragma unroll
            for (int r = 0; r < 16; r++) dot[r] = 0.0f;
            for (int d = 0; d < DIM; d += 4) {
                float4 cv = *(const float4*)(crow + d);
                #pragma unroll
                for (int r = 0; r < 16; r++) {
                    const float* zr = zs + r * DIM + d;
                    dot[r] = fmaf(cv.x, zr[0], dot[r]);
                    dot[r] = fmaf(cv.y, zr[1], dot[r]);
                    dot[r] = fmaf(cv.z, zr[2], dot[r]);
                    dot[r] = fmaf(cv.w, zr[3], dot[r]);
                }
            }
            float c2v = g_c2[code];
            #pragma unroll
            for (int r = 0; r < 16; r++) {
                if (r < nv) {
                    float d = fmaf(dot[r], -2.0f, c2v);
                    unsigned long long key =
                        ((unsigned long long)mapf(d) << 32) | (unsigned)code;
                    atomicMin(&g_min64[rl[r]], key);
                }
            }
        }
    }
}

// extract exact argmin for uncertain rows
__global__ void k_fix(float* __restrict__ out_idx) {
    int i = blockIdx.x * blockDim.x + threadIdx.x;
    if (i >= g_ucnt) return;
    int row = g_ulist[i];
    int idx = (int)(g_min64[row] & 0xFFFFFFFFull);
    g_idx[row] = idx;
    out_idx[row] = (float)idx;
}

// ---------------------------------------------------------------------------
// gather quantized + EMA scatter (8 rows per block)
// ---------------------------------------------------------------------------
__global__ void k_scatter(const float* __restrict__ z, const float* __restrict__ cbk,
                          float* __restrict__ out_q,
                          float* __restrict__ out_avg, float* __restrict__ out_cs) {
    const int tid = threadIdx.x;
    const int row0 = blockIdx.x * 8;
    const float sc = 1.0f - DECAYF;
    #pragma unroll
    for (int r = 0; r < 8; r++) {
        int row = row0 + r;
        int idx = g_idx[row];
        float q = cbk[(size_t)idx * DIM + tid];
        out_q[(size_t)row * DIM + tid] = q;
        atomicAdd(&out_avg[(size_t)idx * DIM + tid],
                  z[(size_t)row * DIM + tid] * sc);
        if (tid == 0) atomicAdd(&out_cs[idx], sc);
    }
}

// ---------------------------------------------------------------------------
__global__ void k_sumn(const float* __restrict__ out_cs) {
    __shared__ float sh[256];
    float s = 0.0f;
    for (int i = threadIdx.x; i < K_CODES; i += 256) s += out_cs[i];
    sh[threadIdx.x] = s;
    __syncthreads();
    for (int o = 128; o; o >>= 1) {
        if (threadIdx.x < o) sh[threadIdx.x] += sh[threadIdx.x + o];
        __syncthreads();
    }
    if (threadIdx.x == 0) g_n = sh[0];
}

__global__ void k_final(const float* __restrict__ out_avg,
                        const float* __restrict__ out_cs,
                        float* __restrict__ out_cb) {
    int k = blockIdx.x;
    float n = g_n;
    float smoothed = (out_cs[k] + EPSF) / (n + (float)K_CODES * EPSF) * n;
    size_t off = (size_t)k * DIM + threadIdx.x;
    out_cb[off] = out_avg[off] / smoothed;
}

// ---------------------------------------------------------------------------
extern "C" void kernel_launch(void* const* d_in, const int* in_sizes, int n_in,
                              void* d_out, int out_size) {
    const float* z_flat   = (const float*)d_in[0];
    const float* codebook = (const float*)d_in[1];
    const float* emb_avg  = (const float*)d_in[2];
    const float* cs_in    = (const float*)d_in[3];

    float* out_q   = (float*)d_out;
    float* out_idx = out_q   + (size_t)N_PTS * DIM;
    float* out_cb  = out_idx + N_PTS;
    float* out_avg = out_cb  + (size_t)K_CODES * DIM;
    float* out_cs  = out_avg + (size_t)K_CODES * DIM;

    cudaFuncSetAttribute(k_approx, cudaFuncAttributeMaxDynamicSharedMemorySize, SM_TOTAL);

    k_zero<<<1, 32>>>();
    k_split_z<<<N_PTS / 8, 256>>>(z_flat);
    k_split_c<<<K_CODES / 8, 256>>>(codebook);
    k_init<<<(K_CODES * DIM + 255) / 256, 256>>>(emb_avg, cs_in, out_avg, out_cs);
    k_approx<<<N_PTS / BM, 256, SM_TOTAL>>>(out_idx);
    k_exact<<<256, 256>>>(z_flat, codebook);
    k_fix<<<128, 256>>>(out_idx);
    k_scatter<<<N_PTS / 8, DIM>>>(z_flat, codebook, out_q, out_avg, out_cs);
    k_sumn<<<1, 256>>>(out_cs);
    k_final<<<K_CODES, DIM>>>(out_avg, out_cs, out_cb);
}

// round 5
// speedup vs baseline: 6.6207x; 2.0220x over previous
#include <cuda_runtime.h>
#include <cuda_fp16.h>
#include <cstdint>
#include <cstddef>

#define N_PTS   32768
#define K_CODES 8192
#define DIM     256
#define DECAYF  0.99f
#define EPSF    1e-5f

#define BM 128
#define BN 128
#define KC 32
#define NKC (DIM / KC)           // 8 chunks per n-tile
#define NNT (K_CODES / BN)       // 64 n-tiles
#define NGC (NNT * NKC)          // 512 chunks total
#define NSTG 4                   // cp.async ring depth

// dynamic smem layout for k_approx (bytes)
#define SM_A     0               // 8 mtiles * 16 ksteps * 32 lanes * 16B = 65536
#define SM_B     65536           // 4 bufs * 10240 (128 rows * 80B padded)
#define SM_BSZ   10240
#define SM_C2    106496          // float[128]
#define SM_R1    107008          // float[128][2]
#define SM_R2    108032
#define SM_R3    109056
#define SM_I1    110080          // int[128][2]
#define SM_I2    111104
#define SM_TOTAL 112128

// device scratch
__device__ __half g_zh[(size_t)N_PTS * DIM];     // 16 MB
__device__ __half g_ch[(size_t)K_CODES * DIM];   // 4 MB
__device__ float  g_c2[K_CODES];
__device__ float  g_zn[(size_t)N_PTS * 2];       // per-row ||zh||, ||zl||
__device__ unsigned g_stats[2];                  // maxC2, maxCl2 (float bits)
__device__ int    g_ucnt;
__device__ int    g_pcnt;
__device__ int    g_ulist[N_PTS];
__device__ int4   g_pairs[N_PTS];
__device__ unsigned long long g_min64[N_PTS];
__device__ int    g_idx[N_PTS];
__device__ float  g_n;

__device__ __forceinline__ uint32_t s2u(const void* p) {
    uint32_t a;
    asm("{ .reg .u64 t; cvta.to.shared.u64 t, %1; cvt.u32.u64 %0, t; }"
        : "=r"(a) : "l"(p));
    return a;
}
__device__ __forceinline__ void atomicMaxF(unsigned* addr, float v) {
    atomicMax(addr, __float_as_uint(v));     // v >= 0
}
__device__ __forceinline__ unsigned mapf(float d) {
    unsigned u = __float_as_uint(d);
    return (u & 0x80000000u) ? ~u : (u | 0x80000000u);
}

// ---------------------------------------------------------------------------
__global__ void k_zero() {
    if (threadIdx.x == 0) { g_ucnt = 0; g_pcnt = 0; }
    if (threadIdx.x < 2) g_stats[threadIdx.x] = 0;
}

// split z -> zh; per-row norms. warp per row.
__global__ void k_split_z(const float* __restrict__ z) {
    int row  = (blockIdx.x * blockDim.x + threadIdx.x) >> 5;
    int lane = threadIdx.x & 31;
    float h2 = 0.0f, l2 = 0.0f;
    const float* src = z + (size_t)row * DIM;
    __half* dst = g_zh + (size_t)row * DIM;
    #pragma unroll
    for (int d = 0; d < DIM / 32; d++) {
        int c = lane + d * 32;
        float v = src[c];
        __half h = __float2half_rn(v);
        float hf = __half2float(h);
        float lf = v - hf;
        dst[c] = h;
        h2 += hf * hf; l2 += lf * lf;
    }
    #pragma unroll
    for (int o = 16; o; o >>= 1) {
        h2 += __shfl_xor_sync(0xffffffffu, h2, o);
        l2 += __shfl_xor_sync(0xffffffffu, l2, o);
    }
    if (lane == 0) {
        g_zn[(size_t)row * 2]     = sqrtf(h2);
        g_zn[(size_t)row * 2 + 1] = sqrtf(l2);
    }
}

// split codebook -> ch; exact c2; global maxima of c2, ||c_lo||^2
__global__ void k_split_c(const float* __restrict__ cbk) {
    __shared__ float sh[2];
    if (threadIdx.x < 2) sh[threadIdx.x] = 0.0f;
    __syncthreads();
    int code = (blockIdx.x * blockDim.x + threadIdx.x) >> 5;
    int lane = threadIdx.x & 31;
    const float* src = cbk + (size_t)code * DIM;
    __half* dst = g_ch + (size_t)code * DIM;
    float c2 = 0.0f, l2 = 0.0f;
    #pragma unroll
    for (int d = 0; d < DIM / 32; d++) {
        int c = lane + d * 32;
        float v = src[c];
        __half h = __float2half_rn(v);
        float lf = v - __half2float(h);
        dst[c] = h;
        c2 += v * v; l2 += lf * lf;
    }
    #pragma unroll
    for (int o = 16; o; o >>= 1) {
        c2 += __shfl_xor_sync(0xffffffffu, c2, o);
        l2 += __shfl_xor_sync(0xffffffffu, l2, o);
    }
    if (lane == 0) {
        g_c2[code] = c2;
        atomicMaxF((unsigned*)&sh[0], c2);
        atomicMaxF((unsigned*)&sh[1], l2);
    }
    __syncthreads();
    if (threadIdx.x == 0) atomicMaxF(&g_stats[0], sh[0]);
    if (threadIdx.x == 1) atomicMaxF(&g_stats[1], sh[1]);
}

// ---------------------------------------------------------------------------
__global__ void k_init(const float* __restrict__ emb_avg,
                       const float* __restrict__ cs_in,
                       float* __restrict__ out_avg,
                       float* __restrict__ out_cs) {
    size_t i = (size_t)blockIdx.x * blockDim.x + threadIdx.x;
    if (i < (size_t)K_CODES * DIM) out_avg[i] = emb_avg[i] * DECAYF;
    if (i < (size_t)K_CODES)       out_cs[i]  = cs_in[i]  * DECAYF;
}

// merge two sorted (b1<=b2<=b3) triples with indices for the first two
__device__ __forceinline__ void merge3(
    float& b1, float& b2, float& b3, int& i1, int& i2,
    float c1, float c2, float c3, int j1, int j2)
{
    if (c1 < b1 || (c1 == b1 && j1 < i1)) {
        float tf; int ti;
        tf = b1; b1 = c1; c1 = tf;  ti = i1; i1 = j1; j1 = ti;
        tf = b2; b2 = c2; c2 = tf;  ti = i2; i2 = j2; j2 = ti;
        tf = b3; b3 = c3; c3 = tf;
    }
    if (c1 < b2 || (c1 == b2 && j1 < i2)) {
        b3 = fminf(b2, c2);
        b2 = c1; i2 = j1;
    } else {
        b3 = fminf(b3, c1);
    }
}

// ---------------------------------------------------------------------------
// fp16 hi*hi GEMM + top-3 argmin with certified per-row margin
// ---------------------------------------------------------------------------
__global__ void __launch_bounds__(256, 2) k_approx(float* __restrict__ out_idx)
{
    extern __shared__ __align__(16) char sm[];
    const uint32_t sb = s2u(sm);
    const int tid  = threadIdx.x;
    const int lane = tid & 31;
    const int wid  = tid >> 5;
    const int wm   = wid & 3;
    const int wn   = wid >> 2;
    const int row0 = blockIdx.x * BM;

    // stage A (128 x 256 halfs) pre-fragment layout
    for (int t = wid; t < 8 * 16; t += 8) {
        const int tmt = t >> 4, ks = t & 15;
        const __half* g = g_zh + (size_t)(row0 + tmt * 16 + (lane >> 2)) * DIM
                        + ks * 16 + (lane & 3) * 2;
        uint32_t r0 = *(const uint32_t*)g;
        uint32_t r1 = *(const uint32_t*)(g + 8 * DIM);
        uint32_t r2 = *(const uint32_t*)(g + 8);
        uint32_t r3 = *(const uint32_t*)(g + 8 * DIM + 8);
        uint32_t addr = sb + SM_A + (uint32_t)(t * 32 + lane) * 16;
        asm volatile("st.shared.v4.b32 [%0], {%1,%2,%3,%4};"
                     :: "r"(addr), "r"(r0), "r"(r1), "r"(r2), "r"(r3));
    }

    float b1[4], b2[4], b3[4];
    int   i1[4], i2[4];
    #pragma unroll
    for (int s = 0; s < 4; s++) {
        b1[s] = b2[s] = b3[s] = 3.4e38f; i1[s] = 0; i2[s] = 0;
    }

    float* c2s = (float*)(sm + SM_C2);

    // prefetch chunks 0..NSTG-2 as separate groups
    #pragma unroll
    for (int p = 0; p < NSTG - 1; p++) {
        const int pc0 = (p >> 3) * BN, pko = (p & 7) * KC;
        const uint32_t bb = sb + SM_B + p * SM_BSZ;
        #pragma unroll
        for (int uu = 0; uu < 2; uu++) {
            int u = tid + uu * 256;
            int r = u >> 2, s = u & 3;
            const __half* src = g_ch + (size_t)(pc0 + r) * DIM + pko + s * 8;
            uint32_t dst = bb + (uint32_t)(r * 80 + s * 16);
            asm volatile("cp.async.cg.shared.global [%0], [%1], 16;"
                         :: "r"(dst), "l"(src));
        }
        asm volatile("cp.async.commit_group;");
    }

    for (int nt0 = 0; nt0 < NNT; nt0++) {
        const int code0 = nt0 * BN;

        float acc[2][8][4];
        #pragma unroll
        for (int mt = 0; mt < 2; mt++)
            #pragma unroll
            for (int nt = 0; nt < 8; nt++)
                #pragma unroll
                for (int q = 0; q < 4; q++) acc[mt][nt][q] = 0.0f;

        for (int kc = 0; kc < NKC; kc++) {
            const int gc = nt0 * NKC + kc;
            asm volatile("cp.async.wait_group %0;" :: "n"(NSTG - 2));
            __syncthreads();

            if (kc == 0 && tid < BN) c2s[tid] = g_c2[code0 + tid];

            // prefetch chunk gc+NSTG-1 into ring slot (empty group at tail)
            {
                const int p = gc + NSTG - 1;
                if (p < NGC) {
                    const int pc0 = (p >> 3) * BN, pko = (p & 7) * KC;
                    const uint32_t bb = sb + SM_B + (p & (NSTG - 1)) * SM_BSZ;
                    #pragma unroll
                    for (int uu = 0; uu < 2; uu++) {
                        int u = tid + uu * 256;
                        int r = u >> 2, s = u & 3;
                        const __half* src = g_ch + (size_t)(pc0 + r) * DIM + pko + s * 8;
                        uint32_t dst = bb + (uint32_t)(r * 80 + s * 16);
                        asm volatile("cp.async.cg.shared.global [%0], [%1], 16;"
                                     :: "r"(dst), "l"(src));
                    }
                }
                asm volatile("cp.async.commit_group;");
            }

            const uint32_t bbase = sb + SM_B + (gc & (NSTG - 1)) * SM_BSZ;
            #pragma unroll
            for (int k2 = 0; k2 < 2; k2++) {
                const int ks = kc * 2 + k2;
                uint32_t a0[4], a1[4];
                {
                    uint32_t addr = sb + SM_A
                        + (uint32_t)(((wm * 2 + 0) * 16 + ks) * 32 + lane) * 16;
                    asm volatile("ld.shared.v4.b32 {%0,%1,%2,%3}, [%4];"
                                 : "=r"(a0[0]), "=r"(a0[1]), "=r"(a0[2]), "=r"(a0[3])
                                 : "r"(addr));
                    addr = sb + SM_A
                        + (uint32_t)(((wm * 2 + 1) * 16 + ks) * 32 + lane) * 16;
                    asm volatile("ld.shared.v4.b32 {%0,%1,%2,%3}, [%4];"
                                 : "=r"(a1[0]), "=r"(a1[1]), "=r"(a1[2]), "=r"(a1[3])
                                 : "r"(addr));
                }
                uint32_t b[16];
                #pragma unroll
                for (int j = 0; j < 4; j++) {
                    int gq = lane >> 3, rr = lane & 7;
                    uint32_t addr = bbase
                        + (uint32_t)((wn * 64 + (2 * j + (gq >> 1)) * 8 + rr) * 80
                                     + k2 * 32 + (gq & 1) * 16);
                    asm volatile("ldmatrix.sync.aligned.m8n8.x4.shared.b16 "
                                 "{%0,%1,%2,%3}, [%4];"
                                 : "=r"(b[4 * j]), "=r"(b[4 * j + 1]),
                                   "=r"(b[4 * j + 2]), "=r"(b[4 * j + 3])
                                 : "r"(addr));
                }
                #pragma unroll
                for (int nt = 0; nt < 8; nt++) {
                    const int bj = (nt >> 1) * 4 + (nt & 1) * 2;
                    asm volatile(
                        "mma.sync.aligned.m16n8k16.row.col.f32.f16.f16.f32 "
                        "{%0,%1,%2,%3}, {%4,%5,%6,%7}, {%8,%9}, {%0,%1,%2,%3};"
                        : "+f"(acc[0][nt][0]), "+f"(acc[0][nt][1]),
                          "+f"(acc[0][nt][2]), "+f"(acc[0][nt][3])
                        : "r"(a0[0]), "r"(a0[1]), "r"(a0[2]), "r"(a0[3]),
                          "r"(b[bj]), "r"(b[bj + 1]));
                    asm volatile(
                        "mma.sync.aligned.m16n8k16.row.col.f32.f16.f16.f32 "
                        "{%0,%1,%2,%3}, {%4,%5,%6,%7}, {%8,%9}, {%0,%1,%2,%3};"
                        : "+f"(acc[1][nt][0]), "+f"(acc[1][nt][1]),
                          "+f"(acc[1][nt][2]), "+f"(acc[1][nt][3])
                        : "r"(a1[0]), "r"(a1[1]), "r"(a1[2]), "r"(a1[3]),
                          "r"(b[bj]), "r"(b[bj + 1]));
                }
            }
        }

        // fold top-3: dist = c2 - 2*dot  (no sync needed before next tile's wait+sync)
        #pragma unroll
        for (int mt = 0; mt < 2; mt++)
            #pragma unroll
            for (int nt = 0; nt < 8; nt++)
                #pragma unroll
                for (int q = 0; q < 4; q++) {
                    int cc = wn * 64 + nt * 8 + (lane & 3) * 2 + (q & 1);
                    float d = fmaf(acc[mt][nt][q], -2.0f, c2s[cc]);
                    int s = mt * 2 + (q >> 1);
                    if (d < b3[s]) {
                        if (d < b1[s]) {
                            b3[s] = b2[s]; b2[s] = b1[s]; i2[s] = i1[s];
                            b1[s] = d; i1[s] = code0 + cc;
                        } else if (d < b2[s]) {
                            b3[s] = b2[s]; b2[s] = d; i2[s] = code0 + cc;
                        } else b3[s] = d;
                    }
                }
    }

    // lane reduce within 4-groups (disjoint code columns, same rows)
    #pragma unroll
    for (int s = 0; s < 4; s++) {
        #pragma unroll
        for (int o = 1; o < 4; o <<= 1) {
            float c1 = __shfl_xor_sync(0xffffffffu, b1[s], o);
            float c2v = __shfl_xor_sync(0xffffffffu, b2[s], o);
            float c3 = __shfl_xor_sync(0xffffffffu, b3[s], o);
            int   j1 = __shfl_xor_sync(0xffffffffu, i1[s], o);
            int   j2 = __shfl_xor_sync(0xffffffffu, i2[s], o);
            merge3(b1[s], b2[s], b3[s], i1[s], i2[s], c1, c2v, c3, j1, j2);
        }
        if ((lane & 3) == 0) {
            int row = wm * 32 + s * 8 + (lane >> 2);
            ((float*)(sm + SM_R1))[row * 2 + wn] = b1[s];
            ((float*)(sm + SM_R2))[row * 2 + wn] = b2[s];
            ((float*)(sm + SM_R3))[row * 2 + wn] = b3[s];
            ((int*)  (sm + SM_I1))[row * 2 + wn] = i1[s];
            ((int*)  (sm + SM_I2))[row * 2 + wn] = i2[s];
        }
    }
    __syncthreads();

    if (tid < BM) {
        float x1 = ((float*)(sm + SM_R1))[tid * 2];
        float x2 = ((float*)(sm + SM_R2))[tid * 2];
        float x3 = ((float*)(sm + SM_R3))[tid * 2];
        int   y1 = ((int*)  (sm + SM_I1))[tid * 2];
        int   y2 = ((int*)  (sm + SM_I2))[tid * 2];
        merge3(x1, x2, x3, y1, y2,
               ((float*)(sm + SM_R1))[tid * 2 + 1],
               ((float*)(sm + SM_R2))[tid * 2 + 1],
               ((float*)(sm + SM_R3))[tid * 2 + 1],
               ((int*)  (sm + SM_I1))[tid * 2 + 1],
               ((int*)  (sm + SM_I2))[tid * 2 + 1]);

        int row = row0 + tid;
        float mC  = sqrtf(__uint_as_float(g_stats[0]));
        float mCl = sqrtf(__uint_as_float(g_stats[1]));
        float nzh = g_zn[(size_t)row * 2];
        float nzl = g_zn[(size_t)row * 2 + 1];
        float margin = 4.0f * (nzh * mCl + nzl * mC) + 0.02f;

        if (x2 - x1 >= margin) {
            g_idx[row] = y1;
            out_idx[row] = (float)y1;
        } else if (x3 - x1 >= margin) {
            int pos = atomicAdd(&g_pcnt, 1);
            g_pairs[pos] = make_int4(row, y1, y2, 0);
        } else {
            int pos = atomicAdd(&g_ucnt, 1);
            g_ulist[pos] = row;
            g_min64[row] = ~0ull;
        }
    }
}

// ---------------------------------------------------------------------------
// exact 2-candidate compare (one warp per uncertain-pair row)
// ---------------------------------------------------------------------------
__global__ void k_pairfix(const float* __restrict__ z, const float* __restrict__ cbk,
                          float* __restrict__ out_idx) {
    int gw   = (blockIdx.x * blockDim.x + threadIdx.x) >> 5;
    int lane = threadIdx.x & 31;
    int nw   = (gridDim.x * blockDim.x) >> 5;
    int cnt  = g_pcnt;
    for (int i = gw; i < cnt; i += nw) {
        int4 p = g_pairs[i];
        const float* zr = z   + (size_t)p.x * DIM + lane * 8;
        const float* ca = cbk + (size_t)p.y * DIM + lane * 8;
        const float* cb = cbk + (size_t)p.z * DIM + lane * 8;
        float da = 0.0f, db = 0.0f;
        #pragma unroll
        for (int q = 0; q < 8; q++) {
            float zv = zr[q];
            da = fmaf(zv, ca[q], da);
            db = fmaf(zv, cb[q], db);
        }
        #pragma unroll
        for (int o = 16; o; o >>= 1) {
            da += __shfl_xor_sync(0xffffffffu, da, o);
            db += __shfl_xor_sync(0xffffffffu, db, o);
        }
        if (lane == 0) {
            float d1 = fmaf(da, -2.0f, g_c2[p.y]);
            float d2 = fmaf(db, -2.0f, g_c2[p.z]);
            int idx = (d2 < d1 || (d2 == d1 && p.z < p.y)) ? p.z : p.y;
            g_idx[p.x] = idx;
            out_idx[p.x] = (float)idx;
        }
    }
}

// ---------------------------------------------------------------------------
// full exact fp32 re-rank (rare rows)
// ---------------------------------------------------------------------------
__global__ void __launch_bounds__(256) k_exact(
    const float* __restrict__ z, const float* __restrict__ cbk)
{
    __shared__ float zs[16 * DIM];
    __shared__ int   rl[16];
    const int tid = threadIdx.x;
    const int ucnt = g_ucnt;
    const int njobs = ((ucnt + 15) >> 4) << 3;

    for (int job = blockIdx.x; job < njobs; job += gridDim.x) {
        const int rg = job >> 3;
        const int cs = job & 7;
        const int nv = min(16, ucnt - rg * 16);

        __syncthreads();
        if (tid < 16) rl[tid] = (tid < nv) ? g_ulist[rg * 16 + tid] : 0;
        __syncthreads();
        for (int r = 0; r < 16; r++) {
            zs[r * DIM + tid] = (r < nv) ? z[(size_t)rl[r] * DIM + tid] : 0.0f;
        }
        __syncthreads();

        #pragma unroll 1
        for (int cc = 0; cc < 4; cc++) {
            const int code = cs * 1024 + cc * 256 + tid;
            const float* crow = cbk + (size_t)code * DIM;
            float dot[16];
            #pragma unroll
            for (int r = 0; r < 16; r++) dot[r] = 0.0f;
            for (int d = 0; d < DIM; d += 4) {
                float4 cv = *(const float4*)(crow + d);
                #pragma unroll
                for (int r = 0; r < 16; r++) {
                    const float* zr = zs + r * DIM + d;
                    dot[r] = fmaf(cv.x, zr[0], dot[r]);
                    dot[r] = fmaf(cv.y, zr[1], dot[r]);
                    dot[r] = fmaf(cv.z, zr[2], dot[r]);
                    dot[r] = fmaf(cv.w, zr[3], dot[r]);
                }
            }
            float c2v = g_c2[code];
            #pragma unroll
            for (int r = 0; r < 16; r++) {
                if (r < nv) {
                    float d = fmaf(dot[r], -2.0f, c2v);
                    unsigned long long key =
                        ((unsigned long long)mapf(d) << 32) | (unsigned)code;
                    atomicMin(&g_min64[rl[r]], key);
                }
            }
        }
    }
}

__global__ void k_fix(float* __restrict__ out_idx) {
    int i = blockIdx.x * blockDim.x + threadIdx.x;
    if (i >= g_ucnt) return;
    int row = g_ulist[i];
    int idx = (int)(g_min64[row] & 0xFFFFFFFFull);
    g_idx[row] = idx;
    out_idx[row] = (float)idx;
}

// ---------------------------------------------------------------------------
__global__ void k_scatter(const float* __restrict__ z, const float* __restrict__ cbk,
                          float* __restrict__ out_q,
                          float* __restrict__ out_avg, float* __restrict__ out_cs) {
    const int tid = threadIdx.x;
    const int row0 = blockIdx.x * 8;
    const float sc = 1.0f - DECAYF;
    #pragma unroll
    for (int r = 0; r < 8; r++) {
        int row = row0 + r;
        int idx = g_idx[row];
        float q = cbk[(size_t)idx * DIM + tid];
        out_q[(size_t)row * DIM + tid] = q;
        atomicAdd(&out_avg[(size_t)idx * DIM + tid],
                  z[(size_t)row * DIM + tid] * sc);
        if (tid == 0) atomicAdd(&out_cs[idx], sc);
    }
}

// ---------------------------------------------------------------------------
__global__ void k_sumn(const float* __restrict__ out_cs) {
    __shared__ float sh[256];
    float s = 0.0f;
    for (int i = threadIdx.x; i < K_CODES; i += 256) s += out_cs[i];
    sh[threadIdx.x] = s;
    __syncthreads();
    for (int o = 128; o; o >>= 1) {
        if (threadIdx.x < o) sh[threadIdx.x] += sh[threadIdx.x + o];
        __syncthreads();
    }
    if (threadIdx.x == 0) g_n = sh[0];
}

__global__ void k_final(const float* __restrict__ out_avg,
                        const float* __restrict__ out_cs,
                        float* __restrict__ out_cb) {
    int k = blockIdx.x;
    float n = g_n;
    float smoothed = (out_cs[k] + EPSF) / (n + (float)K_CODES * EPSF) * n;
    size_t off = (size_t)k * DIM + threadIdx.x;
    out_cb[off] = out_avg[off] / smoothed;
}

// ---------------------------------------------------------------------------
extern "C" void kernel_launch(void* const* d_in, const int* in_sizes, int n_in,
                              void* d_out, int out_size) {
    const float* z_flat   = (const float*)d_in[0];
    const float* codebook = (const float*)d_in[1];
    const float* emb_avg  = (const float*)d_in[2];
    const float* cs_in    = (const float*)d_in[3];

    float* out_q   = (float*)d_out;
    float* out_idx = out_q   + (size_t)N_PTS * DIM;
    float* out_cb  = out_idx + N_PTS;
    float* out_avg = out_cb  + (size_t)K_CODES * DIM;
    float* out_cs  = out_avg + (size_t)K_CODES * DIM;

    cudaFuncSetAttribute(k_approx, cudaFuncAttributeMaxDynamicSharedMemorySize, SM_TOTAL);

    k_zero<<<1, 32>>>();
    k_split_z<<<N_PTS / 8, 256>>>(z_flat);
    k_split_c<<<K_CODES / 8, 256>>>(codebook);
    k_init<<<(K_CODES * DIM + 255) / 256, 256>>>(emb_avg, cs_in, out_avg, out_cs);
    k_approx<<<N_PTS / BM, 256, SM_TOTAL>>>(out_idx);
    k_pairfix<<<64, 256>>>(z_flat, codebook, out_idx);
    k_exact<<<256, 256>>>(z_flat, codebook);
    k_fix<<<128, 256>>>(out_idx);
    k_scatter<<<N_PTS / 8, DIM>>>(z_flat, codebook, out_q, out_avg, out_cs);
    k_sumn<<<1, 256>>>(out_cs);
    k_final<<<K_CODES, DIM>>>(out_avg, out_cs, out_cb);
}